// round 12
// baseline (speedup 1.0000x reference)
#include <cuda_runtime.h>
#include <cuda_fp16.h>
#include <cstdint>
#include <cstddef>

#define MAXN 100000
#define MAXE 1000000
#define NFEAT 64
#define NGRAPH 64

// ---------------- device scratch ----------------
__device__ __align__(128) float   g_A[(size_t)MAXN * NFEAT];   // node features h (fp32)
__device__ __align__(128) __half2 g_Bh[(size_t)MAXN * 32];     // (h@W)*dinv fp16; 128B/row = 1 L2 line
__device__ int     g_cnt[MAXN];
__device__ int     g_excl[MAXN];
__device__ int     g_off[MAXN + 1];
__device__ int     g_cur[MAXN];
__device__ int     g_srcs[MAXE];
__device__ float   g_dinv[MAXN];
__device__ int     g_bsum[128];
__device__ int     g_bbase[128];
__device__ float   g_sums[NGRAPH * NFEAT];
__device__ int     g_gcnt[NGRAPH];

// ---------------- f32x2 packed FMA ----------------
__device__ __forceinline__ unsigned long long fma_f32x2(unsigned long long a,
                                                        unsigned long long b,
                                                        unsigned long long c) {
    unsigned long long d;
    asm("fma.rn.f32x2 %0, %1, %2, %3;" : "=l"(d) : "l"(a), "l"(b), "l"(c));
    return d;
}
__device__ __forceinline__ unsigned long long pack2(float x, float y) {
    unsigned long long d;
    asm("mov.b64 %0, {%1, %2};" : "=l"(d) : "f"(x), "f"(y));
    return d;
}

// ---------------- setup kernels ----------------
__global__ void k_zero(int N) {
    int i = blockIdx.x * blockDim.x + threadIdx.x;
    if (i < N) g_cnt[i] = 0;
    if (i < NGRAPH * NFEAT) g_sums[i] = 0.f;
    if (i < NGRAPH) g_gcnt[i] = 0;
}

__global__ void k_hist(const int* __restrict__ ei, int E) {
    int e = blockIdx.x * blockDim.x + threadIdx.x;
    if (e < E) atomicAdd(&g_cnt[ei[E + e]], 1);
}

__global__ void k_dinv(int N) {
    int i = blockIdx.x * blockDim.x + threadIdx.x;
    if (i < N) g_dinv[i] = rsqrtf((float)(g_cnt[i] + 1));  // +1 self loop
}

__global__ void k_scan1(int N) {
    __shared__ int sm[1024];
    int t = threadIdx.x;
    int i = blockIdx.x * 1024 + t;
    int v = (i < N) ? g_cnt[i] : 0;
    sm[t] = v;
    __syncthreads();
    #pragma unroll
    for (int d = 1; d < 1024; d <<= 1) {
        int xv = (t >= d) ? sm[t - d] : 0;
        __syncthreads();
        sm[t] += xv;
        __syncthreads();
    }
    if (i < N) g_excl[i] = sm[t] - v;
    if (t == 1023) g_bsum[blockIdx.x] = sm[1023];
}

__global__ void k_scan2(int nb, int N) {
    __shared__ int sm[128];
    int t = threadIdx.x;
    int v = (t < nb) ? g_bsum[t] : 0;
    sm[t] = v;
    __syncthreads();
    #pragma unroll
    for (int d = 1; d < 128; d <<= 1) {
        int xv = (t >= d) ? sm[t - d] : 0;
        __syncthreads();
        sm[t] += xv;
        __syncthreads();
    }
    if (t < nb) g_bbase[t] = sm[t] - v;
    if (t == 127) g_off[N] = sm[127];
}

__global__ void k_scan3(int N) {
    int i = blockIdx.x * 1024 + threadIdx.x;
    if (i < N) {
        int o = g_excl[i] + g_bbase[blockIdx.x];
        g_off[i] = o;
        g_cur[i] = o;
    }
}

__global__ void k_place(const int* __restrict__ ei, int E) {
    int e = blockIdx.x * blockDim.x + threadIdx.x;
    if (e < E) {
        int s = ei[e];
        int d = ei[E + e];
        int p = atomicAdd(&g_cur[d], 1);
        g_srcs[p] = s;
    }
}

// ---------------- GEMM: g_Bh = half((X @ W) * dinv) ----------------
// 64x64 tile, 256 threads; thread = 2 rows x 8 cols (R6 memory layout, leaner
// instruction mix). Per k-step: 2 LDS.128 (W as ulonglong2, no pack MOVs) +
// 2 broadcast LDS.32 (x) + 2 dup MOVs + 8 FFMA2 = 14 instrs.
// smem 33KB, ~50 regs -> same occupancy envelope as the 27us R6 version.
__global__ void __launch_bounds__(256) k_gemm(const float* __restrict__ Xext,
                                              const float* __restrict__ W,
                                              int N, int useExt) {
    __shared__ float xs[64][65];                  // [row][k] scalar (broadcast reads)
    __shared__ __align__(16) float ws[64][64];    // [k][n]
    const float* __restrict__ X = useExt ? Xext : g_A;
    int t = threadIdx.x;
    int base = blockIdx.x * 64;

    {   // W: vector copy
        const float4* w4 = (const float4*)W;
        float4* s4 = (float4*)&ws[0][0];
        #pragma unroll
        for (int q = 0; q < 4; q++) s4[q * 256 + t] = w4[q * 256 + t];
    }
    #pragma unroll
    for (int it = 0; it < 4; it++) {   // X: coalesced load, scalar store
        int q = it * 256 + t;
        int row = q >> 4;
        int kc = (q & 15) << 2;
        float4 v = make_float4(0.f, 0.f, 0.f, 0.f);
        if (base + row < N) v = *(const float4*)(X + (size_t)(base + row) * 64 + kc);
        xs[row][kc + 0] = v.x; xs[row][kc + 1] = v.y;
        xs[row][kc + 2] = v.z; xs[row][kc + 3] = v.w;
    }
    __syncthreads();

    int c = t & 7;            // col group: cols 8c..8c+7
    int r = t >> 3;           // row group: rows 2r, 2r+1
    int row0 = r << 1;
    int col0 = c << 3;
    unsigned long long acc[2][4];   // [row j][col pair p]
    #pragma unroll
    for (int j = 0; j < 2; j++)
        #pragma unroll
        for (int p = 0; p < 4; p++) acc[j][p] = 0ull;

    #pragma unroll 8
    for (int k = 0; k < 64; k++) {
        ulonglong2 wa = *(const ulonglong2*)&ws[k][col0];       // cols 8c..8c+3
        ulonglong2 wb = *(const ulonglong2*)&ws[k][col0 + 4];   // cols 8c+4..8c+7
        float xv0 = xs[row0][k];
        float xv1 = xs[row0 + 1][k];
        unsigned long long x0 = pack2(xv0, xv0);
        unsigned long long x1 = pack2(xv1, xv1);
        acc[0][0] = fma_f32x2(x0, wa.x, acc[0][0]);
        acc[0][1] = fma_f32x2(x0, wa.y, acc[0][1]);
        acc[0][2] = fma_f32x2(x0, wb.x, acc[0][2]);
        acc[0][3] = fma_f32x2(x0, wb.y, acc[0][3]);
        acc[1][0] = fma_f32x2(x1, wa.x, acc[1][0]);
        acc[1][1] = fma_f32x2(x1, wa.y, acc[1][1]);
        acc[1][2] = fma_f32x2(x1, wb.x, acc[1][2]);
        acc[1][3] = fma_f32x2(x1, wb.y, acc[1][3]);
    }

    #pragma unroll
    for (int j = 0; j < 2; j++) {
        int row = base + row0 + j;
        if (row < N) {
            float dv = g_dinv[row];
            float2 a0 = *reinterpret_cast<float2*>(&acc[j][0]);
            float2 a1 = *reinterpret_cast<float2*>(&acc[j][1]);
            float2 a2 = *reinterpret_cast<float2*>(&acc[j][2]);
            float2 a3 = *reinterpret_cast<float2*>(&acc[j][3]);
            __half2 h0 = __floats2half2_rn(a0.x * dv, a0.y * dv);
            __half2 h1 = __floats2half2_rn(a1.x * dv, a1.y * dv);
            __half2 h2 = __floats2half2_rn(a2.x * dv, a2.y * dv);
            __half2 h3 = __floats2half2_rn(a3.x * dv, a3.y * dv);
            uint4 pk;
            pk.x = *(unsigned*)&h0; pk.y = *(unsigned*)&h1;
            pk.z = *(unsigned*)&h2; pk.w = *(unsigned*)&h3;
            // cols 8c..8c+7 -> half2 index 4c -> uint4 index c within the row
            *(uint4*)&g_Bh[(size_t)row * 32 + (c << 2)] = pk;
        }
    }
}

// ---------------- aggregation: A[i] = dinv[i]*(B[i] + sum B[src]) + b ----------------
// 4 nodes per warp; 8 lanes per node, each lane owns 16B (uint4 = 4 half2) of
// the 128B row. fp16 pairwise tree over 4 edges, fp32 accumulate.
__device__ __forceinline__ void acc_h2(float2& a, __half2 h) {
    float2 f = __half22float2(h);
    a.x += f.x; a.y += f.y;
}

__global__ void __launch_bounds__(256) k_agg(const float* __restrict__ bias,
                                             int relu, int N) {
    int warp = (blockIdx.x * blockDim.x + threadIdx.x) >> 5;
    int lane = threadIdx.x & 31;
    int grp  = lane >> 3;          // 0..3
    int sub  = lane & 7;           // 0..7
    int node = warp * 4 + grp;
    bool active = node < N;
    int nsafe = active ? node : 0;

    const uint4* __restrict__ B4 = (const uint4*)g_Bh;   // B4[node*8 + sub]
    float2 acc[4] = {{0.f,0.f},{0.f,0.f},{0.f,0.f},{0.f,0.f}};

    {   // self loop
        uint4 sv = B4[(size_t)nsafe * 8 + sub];
        acc_h2(acc[0], *(__half2*)&sv.x);
        acc_h2(acc[1], *(__half2*)&sv.y);
        acc_h2(acc[2], *(__half2*)&sv.z);
        acc_h2(acc[3], *(__half2*)&sv.w);
    }

    int beg = active ? g_off[nsafe] : 0;
    int end = active ? g_off[nsafe + 1] : 0;
    int j = beg;
    for (; j + 4 <= end; j += 4) {
        int s0 = g_srcs[j], s1 = g_srcs[j + 1], s2 = g_srcs[j + 2], s3 = g_srcs[j + 3];
        uint4 a = B4[(size_t)s0 * 8 + sub];
        uint4 b = B4[(size_t)s1 * 8 + sub];
        uint4 cc = B4[(size_t)s2 * 8 + sub];
        uint4 d = B4[(size_t)s3 * 8 + sub];
        __half2 t0 = __hadd2(__hadd2(*(__half2*)&a.x, *(__half2*)&b.x),
                             __hadd2(*(__half2*)&cc.x, *(__half2*)&d.x));
        __half2 t1 = __hadd2(__hadd2(*(__half2*)&a.y, *(__half2*)&b.y),
                             __hadd2(*(__half2*)&cc.y, *(__half2*)&d.y));
        __half2 t2 = __hadd2(__hadd2(*(__half2*)&a.z, *(__half2*)&b.z),
                             __hadd2(*(__half2*)&cc.z, *(__half2*)&d.z));
        __half2 t3 = __hadd2(__hadd2(*(__half2*)&a.w, *(__half2*)&b.w),
                             __hadd2(*(__half2*)&cc.w, *(__half2*)&d.w));
        acc_h2(acc[0], t0); acc_h2(acc[1], t1);
        acc_h2(acc[2], t2); acc_h2(acc[3], t3);
    }
    if (j + 2 <= end) {
        int s0 = g_srcs[j], s1 = g_srcs[j + 1];
        uint4 a = B4[(size_t)s0 * 8 + sub];
        uint4 b = B4[(size_t)s1 * 8 + sub];
        acc_h2(acc[0], __hadd2(*(__half2*)&a.x, *(__half2*)&b.x));
        acc_h2(acc[1], __hadd2(*(__half2*)&a.y, *(__half2*)&b.y));
        acc_h2(acc[2], __hadd2(*(__half2*)&a.z, *(__half2*)&b.z));
        acc_h2(acc[3], __hadd2(*(__half2*)&a.w, *(__half2*)&b.w));
        j += 2;
    }
    if (j < end) {
        uint4 a = B4[(size_t)g_srcs[j] * 8 + sub];
        acc_h2(acc[0], *(__half2*)&a.x);
        acc_h2(acc[1], *(__half2*)&a.y);
        acc_h2(acc[2], *(__half2*)&a.z);
        acc_h2(acc[3], *(__half2*)&a.w);
    }

    if (active) {
        float dv = g_dinv[node];
        const float4* bp = (const float4*)(bias + sub * 8);
        float4 b0 = bp[0], b1 = bp[1];
        float4 o0 = make_float4(fmaf(acc[0].x, dv, b0.x), fmaf(acc[0].y, dv, b0.y),
                                fmaf(acc[1].x, dv, b0.z), fmaf(acc[1].y, dv, b0.w));
        float4 o1 = make_float4(fmaf(acc[2].x, dv, b1.x), fmaf(acc[2].y, dv, b1.y),
                                fmaf(acc[3].x, dv, b1.z), fmaf(acc[3].y, dv, b1.w));
        if (relu) {
            o0.x = fmaxf(o0.x, 0.f); o0.y = fmaxf(o0.y, 0.f);
            o0.z = fmaxf(o0.z, 0.f); o0.w = fmaxf(o0.w, 0.f);
            o1.x = fmaxf(o1.x, 0.f); o1.y = fmaxf(o1.y, 0.f);
            o1.z = fmaxf(o1.z, 0.f); o1.w = fmaxf(o1.w, 0.f);
        }
        float4* outp = (float4*)(g_A + (size_t)node * 64 + sub * 8);
        outp[0] = o0; outp[1] = o1;
    }
}

// ---------------- mean pool (batch sorted) ----------------
__global__ void __launch_bounds__(256) k_pool(const int* __restrict__ batch, int N) {
    int warp = (blockIdx.x * blockDim.x + threadIdx.x) >> 5;
    int lane = threadIdx.x & 31;
    int n0 = warp * 32;
    if (n0 >= N) return;
    int nend = min(n0 + 32, N);
    const float2* __restrict__ A2 = (const float2*)g_A;
    float2 acc = make_float2(0.f, 0.f);
    int cur = batch[n0];
    int cnt = 0;
    for (int n = n0; n < nend; n++) {
        int g = batch[n];
        if (g != cur) {
            atomicAdd(&g_sums[cur * 64 + 2 * lane], acc.x);
            atomicAdd(&g_sums[cur * 64 + 2 * lane + 1], acc.y);
            if (lane == 0) atomicAdd(&g_gcnt[cur], cnt);
            acc = make_float2(0.f, 0.f); cnt = 0; cur = g;
        }
        float2 v = A2[(size_t)n * 32 + lane];
        acc.x += v.x; acc.y += v.y; cnt++;
    }
    atomicAdd(&g_sums[cur * 64 + 2 * lane], acc.x);
    atomicAdd(&g_sums[cur * 64 + 2 * lane + 1], acc.y);
    if (lane == 0) atomicAdd(&g_gcnt[cur], cnt);
}

__global__ void k_final(const float* __restrict__ Wlin,
                        const float* __restrict__ blin,
                        float* __restrict__ out) {
    int t = threadIdx.x;
    if (t >= NGRAPH * 2) return;
    int g = t >> 1, o = t & 1;
    float cnt = fmaxf((float)g_gcnt[g], 1.f);
    float s = 0.f;
    #pragma unroll
    for (int f = 0; f < 64; f++) s += g_sums[g * 64 + f] * Wlin[f * 2 + o];
    out[g * 2 + o] = s / cnt + blin[o];
}

// ---------------- launch ----------------
extern "C" void kernel_launch(void* const* d_in, const int* in_sizes, int n_in,
                              void* d_out, int out_size) {
    const float* x     = (const float*)d_in[0];
    const int*   ei    = (const int*)d_in[1];
    const int*   batch = (const int*)d_in[2];
    const float* W1 = (const float*)d_in[3];
    const float* b1 = (const float*)d_in[4];
    const float* W2 = (const float*)d_in[5];
    const float* b2 = (const float*)d_in[6];
    const float* W3 = (const float*)d_in[7];
    const float* b3 = (const float*)d_in[8];
    const float* Wl = (const float*)d_in[9];
    const float* bl = (const float*)d_in[10];
    float* out = (float*)d_out;

    int N = in_sizes[0] / NFEAT;   // 100000
    int E = in_sizes[1] / 2;       // 1000000
    int nb = (N + 1023) / 1024;

    int gemmBlocks = (N + 63) / 64;
    int aggBlocks  = (N + 31) / 32;   // 8 warps x 4 nodes per block

    // CSR build; gemm1 in launch slot 4 (profiler captures launch #4)
    k_zero<<<(N + 255) / 256, 256>>>(N);
    k_hist<<<(E + 255) / 256, 256>>>(ei, E);
    k_dinv<<<(N + 255) / 256, 256>>>(N);
    k_gemm<<<gemmBlocks, 256>>>(x, W1, N, 1);       // launch #4
    k_scan1<<<nb, 1024>>>(N);
    k_scan2<<<1, 128>>>(nb, N);
    k_scan3<<<nb, 1024>>>(N);
    k_place<<<(E + 255) / 256, 256>>>(ei, E);

    k_agg<<<aggBlocks, 256>>>(b1, 1, N);
    k_gemm<<<gemmBlocks, 256>>>(nullptr, W2, N, 0);
    k_agg<<<aggBlocks, 256>>>(b2, 1, N);
    k_gemm<<<gemmBlocks, 256>>>(nullptr, W3, N, 0);
    k_agg<<<aggBlocks, 256>>>(b3, 0, N);

    int poolWarps = (N + 31) / 32;
    k_pool<<<(poolWarps + 7) / 8, 256>>>(batch, N);
    k_final<<<1, 128>>>(Wl, bl, out);
}

// round 13
// speedup vs baseline: 1.5074x; 1.5074x over previous
#include <cuda_runtime.h>
#include <cuda_fp16.h>
#include <cstdint>
#include <cstddef>

#define MAXN 100000
#define MAXE 1000000
#define NFEAT 64
#define NGRAPH 64

// ---------------- device scratch ----------------
__device__ __align__(128) float   g_A[(size_t)MAXN * NFEAT];   // node features h (fp32)
__device__ __align__(128) __half2 g_Bh[(size_t)MAXN * 32];     // (h@W)*dinv fp16; 128B/row = 1 L2 line
__device__ int     g_cnt[MAXN];
__device__ int     g_excl[MAXN];
__device__ int     g_off[MAXN + 1];
__device__ int     g_cur[MAXN];
__device__ int     g_srcs[MAXE];
__device__ float   g_dinv[MAXN];
__device__ int     g_bsum[128];
__device__ int     g_bbase[128];
__device__ float   g_sums[NGRAPH * NFEAT];
__device__ int     g_gcnt[NGRAPH];

// ---------------- f32x2 packed FMA ----------------
__device__ __forceinline__ unsigned long long fma_f32x2(unsigned long long a,
                                                        unsigned long long b,
                                                        unsigned long long c) {
    unsigned long long d;
    asm("fma.rn.f32x2 %0, %1, %2, %3;" : "=l"(d) : "l"(a), "l"(b), "l"(c));
    return d;
}
__device__ __forceinline__ unsigned long long pack2(float x, float y) {
    unsigned long long d;
    asm("mov.b64 %0, {%1, %2};" : "=l"(d) : "f"(x), "f"(y));
    return d;
}

// ---------------- setup kernels ----------------
__global__ void k_zero(int N) {
    int i = blockIdx.x * blockDim.x + threadIdx.x;
    if (i < N) g_cnt[i] = 0;
    if (i < NGRAPH * NFEAT) g_sums[i] = 0.f;
    if (i < NGRAPH) g_gcnt[i] = 0;
}

__global__ void k_hist(const int* __restrict__ ei, int E) {
    int e = blockIdx.x * blockDim.x + threadIdx.x;
    if (e < E) atomicAdd(&g_cnt[ei[E + e]], 1);
}

__global__ void k_dinv(int N) {
    int i = blockIdx.x * blockDim.x + threadIdx.x;
    if (i < N) g_dinv[i] = rsqrtf((float)(g_cnt[i] + 1));  // +1 self loop
}

__global__ void k_scan1(int N) {
    __shared__ int sm[1024];
    int t = threadIdx.x;
    int i = blockIdx.x * 1024 + t;
    int v = (i < N) ? g_cnt[i] : 0;
    sm[t] = v;
    __syncthreads();
    #pragma unroll
    for (int d = 1; d < 1024; d <<= 1) {
        int xv = (t >= d) ? sm[t - d] : 0;
        __syncthreads();
        sm[t] += xv;
        __syncthreads();
    }
    if (i < N) g_excl[i] = sm[t] - v;
    if (t == 1023) g_bsum[blockIdx.x] = sm[1023];
}

__global__ void k_scan2(int nb, int N) {
    __shared__ int sm[128];
    int t = threadIdx.x;
    int v = (t < nb) ? g_bsum[t] : 0;
    sm[t] = v;
    __syncthreads();
    #pragma unroll
    for (int d = 1; d < 128; d <<= 1) {
        int xv = (t >= d) ? sm[t - d] : 0;
        __syncthreads();
        sm[t] += xv;
        __syncthreads();
    }
    if (t < nb) g_bbase[t] = sm[t] - v;
    if (t == 127) g_off[N] = sm[127];
}

__global__ void k_scan3(int N) {
    int i = blockIdx.x * 1024 + threadIdx.x;
    if (i < N) {
        int o = g_excl[i] + g_bbase[blockIdx.x];
        g_off[i] = o;
        g_cur[i] = o;
    }
}

__global__ void k_place(const int* __restrict__ ei, int E) {
    int e = blockIdx.x * blockDim.x + threadIdx.x;
    if (e < E) {
        int s = ei[e];
        int d = ei[E + e];
        int p = atomicAdd(&g_cur[d], 1);
        g_srcs[p] = s;
    }
}

// ---------------- GEMM: g_Bh = half((X @ W) * dinv) ----------------
// R6-exact structure (empirically fastest of 4 tried): 64x64 tile, 256 threads
// as 16x16; thread = 4 rows x 4 cols. xs[row][k] reads are warp-broadcast
// LDS.32; W read as one LDS.128 per k then packed via MOV.
__global__ void __launch_bounds__(256) k_gemm(const float* __restrict__ Xext,
                                              const float* __restrict__ W,
                                              int N, int useExt) {
    __shared__ float xs[64][65];
    __shared__ __align__(16) float ws[64][64];
    const float* __restrict__ X = useExt ? Xext : g_A;
    int t = threadIdx.x;
    int base = blockIdx.x * 64;

    {
        const float4* w4 = (const float4*)W;
        float4* s4 = (float4*)&ws[0][0];
        #pragma unroll
        for (int q = 0; q < 4; q++) s4[q * 256 + t] = w4[q * 256 + t];
    }
    #pragma unroll
    for (int it = 0; it < 4; it++) {
        int q = it * 256 + t;
        int row = q >> 4;
        int kc = (q & 15) << 2;
        float4 v = make_float4(0.f, 0.f, 0.f, 0.f);
        if (base + row < N) v = *(const float4*)(X + (size_t)(base + row) * 64 + kc);
        xs[row][kc + 0] = v.x; xs[row][kc + 1] = v.y;
        xs[row][kc + 2] = v.z; xs[row][kc + 3] = v.w;
    }
    __syncthreads();

    int r = t >> 4;   // rows 4r..4r+3
    int c = t & 15;   // cols 4c..4c+3
    unsigned long long acc[4][2];
    #pragma unroll
    for (int j = 0; j < 4; j++) { acc[j][0] = 0ull; acc[j][1] = 0ull; }

    #pragma unroll 8
    for (int k = 0; k < 64; k++) {
        const float4 wv = *(const float4*)&ws[k][c << 2];
        unsigned long long w01 = pack2(wv.x, wv.y);
        unsigned long long w23 = pack2(wv.z, wv.w);
        #pragma unroll
        for (int j = 0; j < 4; j++) {
            float xv = xs[(r << 2) + j][k];
            unsigned long long xd = pack2(xv, xv);
            acc[j][0] = fma_f32x2(xd, w01, acc[j][0]);
            acc[j][1] = fma_f32x2(xd, w23, acc[j][1]);
        }
    }
    #pragma unroll
    for (int j = 0; j < 4; j++) {
        int row = base + (r << 2) + j;
        if (row < N) {
            float dv = g_dinv[row];
            float2 a0 = *reinterpret_cast<float2*>(&acc[j][0]);  // cols 4c,4c+1
            float2 a1 = *reinterpret_cast<float2*>(&acc[j][1]);  // cols 4c+2,4c+3
            __half2 h01 = __floats2half2_rn(a0.x * dv, a0.y * dv);
            __half2 h23 = __floats2half2_rn(a1.x * dv, a1.y * dv);
            uint2 pk = make_uint2(*(unsigned*)&h01, *(unsigned*)&h23);
            *(uint2*)&g_Bh[(size_t)row * 32 + (c << 1)] = pk;
        }
    }
}

// ---------------- aggregation: A[i] = dinv[i]*(B[i] + sum B[src]) + b ----------------
// 4 nodes per warp; 8 lanes per node, each lane owns 16B (uint4 = 4 half2) of
// the 128B row. fp16 pairwise tree over 4 edges, fp32 accumulate.
__device__ __forceinline__ void acc_h2(float2& a, __half2 h) {
    float2 f = __half22float2(h);
    a.x += f.x; a.y += f.y;
}

__global__ void __launch_bounds__(256) k_agg(const float* __restrict__ bias,
                                             int relu, int N) {
    int warp = (blockIdx.x * blockDim.x + threadIdx.x) >> 5;
    int lane = threadIdx.x & 31;
    int grp  = lane >> 3;          // 0..3
    int sub  = lane & 7;           // 0..7
    int node = warp * 4 + grp;
    bool active = node < N;
    int nsafe = active ? node : 0;

    const uint4* __restrict__ B4 = (const uint4*)g_Bh;   // B4[node*8 + sub]
    float2 acc[4] = {{0.f,0.f},{0.f,0.f},{0.f,0.f},{0.f,0.f}};

    {   // self loop
        uint4 sv = B4[(size_t)nsafe * 8 + sub];
        acc_h2(acc[0], *(__half2*)&sv.x);
        acc_h2(acc[1], *(__half2*)&sv.y);
        acc_h2(acc[2], *(__half2*)&sv.z);
        acc_h2(acc[3], *(__half2*)&sv.w);
    }

    int beg = active ? g_off[nsafe] : 0;
    int end = active ? g_off[nsafe + 1] : 0;
    int j = beg;
    for (; j + 4 <= end; j += 4) {
        int s0 = g_srcs[j], s1 = g_srcs[j + 1], s2 = g_srcs[j + 2], s3 = g_srcs[j + 3];
        uint4 a = B4[(size_t)s0 * 8 + sub];
        uint4 b = B4[(size_t)s1 * 8 + sub];
        uint4 cc = B4[(size_t)s2 * 8 + sub];
        uint4 d = B4[(size_t)s3 * 8 + sub];
        __half2 t0 = __hadd2(__hadd2(*(__half2*)&a.x, *(__half2*)&b.x),
                             __hadd2(*(__half2*)&cc.x, *(__half2*)&d.x));
        __half2 t1 = __hadd2(__hadd2(*(__half2*)&a.y, *(__half2*)&b.y),
                             __hadd2(*(__half2*)&cc.y, *(__half2*)&d.y));
        __half2 t2 = __hadd2(__hadd2(*(__half2*)&a.z, *(__half2*)&b.z),
                             __hadd2(*(__half2*)&cc.z, *(__half2*)&d.z));
        __half2 t3 = __hadd2(__hadd2(*(__half2*)&a.w, *(__half2*)&b.w),
                             __hadd2(*(__half2*)&cc.w, *(__half2*)&d.w));
        acc_h2(acc[0], t0); acc_h2(acc[1], t1);
        acc_h2(acc[2], t2); acc_h2(acc[3], t3);
    }
    if (j + 2 <= end) {
        int s0 = g_srcs[j], s1 = g_srcs[j + 1];
        uint4 a = B4[(size_t)s0 * 8 + sub];
        uint4 b = B4[(size_t)s1 * 8 + sub];
        acc_h2(acc[0], __hadd2(*(__half2*)&a.x, *(__half2*)&b.x));
        acc_h2(acc[1], __hadd2(*(__half2*)&a.y, *(__half2*)&b.y));
        acc_h2(acc[2], __hadd2(*(__half2*)&a.z, *(__half2*)&b.z));
        acc_h2(acc[3], __hadd2(*(__half2*)&a.w, *(__half2*)&b.w));
        j += 2;
    }
    if (j < end) {
        uint4 a = B4[(size_t)g_srcs[j] * 8 + sub];
        acc_h2(acc[0], *(__half2*)&a.x);
        acc_h2(acc[1], *(__half2*)&a.y);
        acc_h2(acc[2], *(__half2*)&a.z);
        acc_h2(acc[3], *(__half2*)&a.w);
    }

    if (active) {
        float dv = g_dinv[node];
        const float4* bp = (const float4*)(bias + sub * 8);
        float4 b0 = bp[0], b1 = bp[1];
        float4 o0 = make_float4(fmaf(acc[0].x, dv, b0.x), fmaf(acc[0].y, dv, b0.y),
                                fmaf(acc[1].x, dv, b0.z), fmaf(acc[1].y, dv, b0.w));
        float4 o1 = make_float4(fmaf(acc[2].x, dv, b1.x), fmaf(acc[2].y, dv, b1.y),
                                fmaf(acc[3].x, dv, b1.z), fmaf(acc[3].y, dv, b1.w));
        if (relu) {
            o0.x = fmaxf(o0.x, 0.f); o0.y = fmaxf(o0.y, 0.f);
            o0.z = fmaxf(o0.z, 0.f); o0.w = fmaxf(o0.w, 0.f);
            o1.x = fmaxf(o1.x, 0.f); o1.y = fmaxf(o1.y, 0.f);
            o1.z = fmaxf(o1.z, 0.f); o1.w = fmaxf(o1.w, 0.f);
        }
        float4* outp = (float4*)(g_A + (size_t)node * 64 + sub * 8);
        outp[0] = o0; outp[1] = o1;
    }
}

// ---------------- mean pool (batch sorted) ----------------
__global__ void __launch_bounds__(256) k_pool(const int* __restrict__ batch, int N) {
    int warp = (blockIdx.x * blockDim.x + threadIdx.x) >> 5;
    int lane = threadIdx.x & 31;
    int n0 = warp * 32;
    if (n0 >= N) return;
    int nend = min(n0 + 32, N);
    const float2* __restrict__ A2 = (const float2*)g_A;
    float2 acc = make_float2(0.f, 0.f);
    int cur = batch[n0];
    int cnt = 0;
    for (int n = n0; n < nend; n++) {
        int g = batch[n];
        if (g != cur) {
            atomicAdd(&g_sums[cur * 64 + 2 * lane], acc.x);
            atomicAdd(&g_sums[cur * 64 + 2 * lane + 1], acc.y);
            if (lane == 0) atomicAdd(&g_gcnt[cur], cnt);
            acc = make_float2(0.f, 0.f); cnt = 0; cur = g;
        }
        float2 v = A2[(size_t)n * 32 + lane];
        acc.x += v.x; acc.y += v.y; cnt++;
    }
    atomicAdd(&g_sums[cur * 64 + 2 * lane], acc.x);
    atomicAdd(&g_sums[cur * 64 + 2 * lane + 1], acc.y);
    if (lane == 0) atomicAdd(&g_gcnt[cur], cnt);
}

__global__ void k_final(const float* __restrict__ Wlin,
                        const float* __restrict__ blin,
                        float* __restrict__ out) {
    int t = threadIdx.x;
    if (t >= NGRAPH * 2) return;
    int g = t >> 1, o = t & 1;
    float cnt = fmaxf((float)g_gcnt[g], 1.f);
    float s = 0.f;
    #pragma unroll
    for (int f = 0; f < 64; f++) s += g_sums[g * 64 + f] * Wlin[f * 2 + o];
    out[g * 2 + o] = s / cnt + blin[o];
}

// ---------------- launch ----------------
extern "C" void kernel_launch(void* const* d_in, const int* in_sizes, int n_in,
                              void* d_out, int out_size) {
    const float* x     = (const float*)d_in[0];
    const int*   ei    = (const int*)d_in[1];
    const int*   batch = (const int*)d_in[2];
    const float* W1 = (const float*)d_in[3];
    const float* b1 = (const float*)d_in[4];
    const float* W2 = (const float*)d_in[5];
    const float* b2 = (const float*)d_in[6];
    const float* W3 = (const float*)d_in[7];
    const float* b3 = (const float*)d_in[8];
    const float* Wl = (const float*)d_in[9];
    const float* bl = (const float*)d_in[10];
    float* out = (float*)d_out;

    int N = in_sizes[0] / NFEAT;   // 100000
    int E = in_sizes[1] / 2;       // 1000000
    int nb = (N + 1023) / 1024;

    int gemmBlocks = (N + 63) / 64;
    int aggBlocks  = (N + 31) / 32;   // 8 warps x 4 nodes per block

    // CSR build; gemm1 in launch slot 4 (profiler captures launch #4)
    k_zero<<<(N + 255) / 256, 256>>>(N);
    k_hist<<<(E + 255) / 256, 256>>>(ei, E);
    k_dinv<<<(N + 255) / 256, 256>>>(N);
    k_gemm<<<gemmBlocks, 256>>>(x, W1, N, 1);       // launch #4
    k_scan1<<<nb, 1024>>>(N);
    k_scan2<<<1, 128>>>(nb, N);
    k_scan3<<<nb, 1024>>>(N);
    k_place<<<(E + 255) / 256, 256>>>(ei, E);

    k_agg<<<aggBlocks, 256>>>(b1, 1, N);
    k_gemm<<<gemmBlocks, 256>>>(nullptr, W2, N, 0);
    k_agg<<<aggBlocks, 256>>>(b2, 1, N);
    k_gemm<<<gemmBlocks, 256>>>(nullptr, W3, N, 0);
    k_agg<<<aggBlocks, 256>>>(b3, 0, N);

    int poolWarps = (N + 31) / 32;
    k_pool<<<(poolWarps + 7) / 8, 256>>>(batch, N);
    k_final<<<1, 128>>>(Wl, bl, out);
}

// round 16
// speedup vs baseline: 1.9569x; 1.2981x over previous
#include <cuda_runtime.h>
#include <cuda_fp16.h>
#include <cuda_bf16.h>
#include <cstdint>
#include <cstddef>

#define MAXN 100000
#define MAXE 1000000
#define NFEAT 64
#define NGRAPH 64

// ---------------- device scratch ----------------
__device__ __align__(128) float   g_A[(size_t)MAXN * NFEAT];   // node features h (fp32)
__device__ __align__(128) __half2 g_Bh[(size_t)MAXN * 32];     // (h@W)*dinv fp16; 128B/row
__device__ __align__(16) __nv_bfloat16 g_Wt_hi[3][NFEAT * NFEAT]; // W^T hi bf16 [layer][n*64+k]
__device__ __align__(16) __nv_bfloat16 g_Wt_lo[3][NFEAT * NFEAT]; // W^T lo bf16
__device__ int     g_cnt[MAXN];
__device__ int     g_excl[MAXN];
__device__ int     g_off[MAXN + 1];
__device__ int     g_cur[MAXN];
__device__ int     g_srcs[MAXE];
__device__ float   g_dinv[MAXN];
__device__ int     g_bsum[128];
__device__ int     g_bbase[128];
__device__ float   g_sums[NGRAPH * NFEAT];
__device__ int     g_gcnt[NGRAPH];

// ---------------- setup kernels ----------------
__global__ void k_zero(int N) {
    int i = blockIdx.x * blockDim.x + threadIdx.x;
    if (i < N) g_cnt[i] = 0;
    if (i < NGRAPH * NFEAT) g_sums[i] = 0.f;
    if (i < NGRAPH) g_gcnt[i] = 0;
}

__global__ void k_hist(const int* __restrict__ ei, int E) {
    int e = blockIdx.x * blockDim.x + threadIdx.x;
    if (e < E) atomicAdd(&g_cnt[ei[E + e]], 1);
}

// dinv + W^T split into hi/lo bf16 (Wt[n][k] = W[k][n]; lo = rn(w - float(hi)))
__global__ void k_dinv(int N, const float* __restrict__ W1,
                       const float* __restrict__ W2, const float* __restrict__ W3) {
    int i = blockIdx.x * blockDim.x + threadIdx.x;
    if (i < N) g_dinv[i] = rsqrtf((float)(g_cnt[i] + 1));  // +1 self loop
    if (i < 3 * NFEAT * NFEAT) {
        int l = i >> 12;
        int r = i & 4095;
        int n = r >> 6, k = r & 63;
        const float* Wp = (l == 0) ? W1 : ((l == 1) ? W2 : W3);
        float w = Wp[k * 64 + n];
        __nv_bfloat16 hi = __float2bfloat16(w);
        __nv_bfloat16 lo = __float2bfloat16(w - __bfloat162float(hi));
        g_Wt_hi[l][n * 64 + k] = hi;
        g_Wt_lo[l][n * 64 + k] = lo;
    }
}

__global__ void k_scan1(int N) {
    __shared__ int sm[1024];
    int t = threadIdx.x;
    int i = blockIdx.x * 1024 + t;
    int v = (i < N) ? g_cnt[i] : 0;
    sm[t] = v;
    __syncthreads();
    #pragma unroll
    for (int d = 1; d < 1024; d <<= 1) {
        int xv = (t >= d) ? sm[t - d] : 0;
        __syncthreads();
        sm[t] += xv;
        __syncthreads();
    }
    if (i < N) g_excl[i] = sm[t] - v;
    if (t == 1023) g_bsum[blockIdx.x] = sm[1023];
}

__global__ void k_scan2(int nb, int N) {
    __shared__ int sm[128];
    int t = threadIdx.x;
    int v = (t < nb) ? g_bsum[t] : 0;
    sm[t] = v;
    __syncthreads();
    #pragma unroll
    for (int d = 1; d < 128; d <<= 1) {
        int xv = (t >= d) ? sm[t - d] : 0;
        __syncthreads();
        sm[t] += xv;
        __syncthreads();
    }
    if (t < nb) g_bbase[t] = sm[t] - v;
    if (t == 127) g_off[N] = sm[127];
}

__global__ void k_scan3(int N) {
    int i = blockIdx.x * 1024 + threadIdx.x;
    if (i < N) {
        int o = g_excl[i] + g_bbase[blockIdx.x];
        g_off[i] = o;
        g_cur[i] = o;
    }
}

__global__ void k_place(const int* __restrict__ ei, int E) {
    int e = blockIdx.x * blockDim.x + threadIdx.x;
    if (e < E) {
        int s = ei[e];
        int d = ei[E + e];
        int p = atomicAdd(&g_cur[d], 1);
        g_srcs[p] = s;
    }
}

// ---------------- tensor-core GEMM via mma.sync, split-bf16 (3-MMA emulation) ----------------
// g_Bh = half((X @ W) * dinv). CTA = 128 thr (4 warps), 64-row tile.
// X = Xhi + Xlo, W = Whi + Wlo (bf16 pairs); D += Xhi*Whi + Xhi*Wlo + Xlo*Whi.
// Fragment layout verified in R15 (quantization-level error only).
// Row pad 72 elems (36 banks): quad fragment loads hit 32 distinct banks.
#define XS_PAD 72
__global__ void __launch_bounds__(128) k_gemm_mma(const float* __restrict__ Xext,
                                                  int N, int useExt, int layer) {
    __shared__ __nv_bfloat16 xs_hi[64][XS_PAD];
    __shared__ __nv_bfloat16 xs_lo[64][XS_PAD];
    __shared__ __nv_bfloat16 wt_hi[64][XS_PAD];
    __shared__ __nv_bfloat16 wt_lo[64][XS_PAD];
    const float* __restrict__ X = useExt ? Xext : g_A;
    int t = threadIdx.x;
    int base = blockIdx.x * 64;

    // Stage W^T hi/lo (2048 b32 each), re-padded
    {
        const uint32_t* wh = (const uint32_t*)g_Wt_hi[layer];
        const uint32_t* wl = (const uint32_t*)g_Wt_lo[layer];
        #pragma unroll
        for (int it = 0; it < 16; it++) {
            int i = it * 128 + t;              // b32 index 0..2047
            int n = i >> 5, kp = i & 31;
            *(uint32_t*)&wt_hi[n][kp * 2] = wh[i];
            *(uint32_t*)&wt_lo[n][kp * 2] = wl[i];
        }
    }
    // Stage X fp32 -> hi/lo bf16 (64 rows x 64 cols = 1024 float4)
    #pragma unroll
    for (int it = 0; it < 8; it++) {
        int q = it * 128 + t;
        int row = q >> 4;              // 0..63
        int c4 = (q & 15) << 2;        // col 0..60 step 4
        float4 v = make_float4(0.f, 0.f, 0.f, 0.f);
        if (base + row < N) v = *(const float4*)(X + (size_t)(base + row) * 64 + c4);
        __nv_bfloat162 h0 = __floats2bfloat162_rn(v.x, v.y);
        __nv_bfloat162 h1 = __floats2bfloat162_rn(v.z, v.w);
        __nv_bfloat162 l0 = __floats2bfloat162_rn(v.x - __bfloat162float(h0.x),
                                                  v.y - __bfloat162float(h0.y));
        __nv_bfloat162 l1 = __floats2bfloat162_rn(v.z - __bfloat162float(h1.x),
                                                  v.w - __bfloat162float(h1.y));
        *(uint32_t*)&xs_hi[row][c4 + 0] = *(unsigned*)&h0;
        *(uint32_t*)&xs_hi[row][c4 + 2] = *(unsigned*)&h1;
        *(uint32_t*)&xs_lo[row][c4 + 0] = *(unsigned*)&l0;
        *(uint32_t*)&xs_lo[row][c4 + 2] = *(unsigned*)&l1;
    }
    __syncthreads();

    int w = t >> 5;              // warp 0..3 -> rows w*16..+15
    int lane = t & 31;
    int gid = lane >> 2;         // group 0..7
    int tig = lane & 3;          // thread-in-group 0..3

    float d[8][4];
    #pragma unroll
    for (int c = 0; c < 8; c++)
        #pragma unroll
        for (int q = 0; q < 4; q++) d[c][q] = 0.f;

    int ra = w * 16 + gid;
    #pragma unroll
    for (int ks = 0; ks < 4; ks++) {
        int k0 = ks * 16 + tig * 2;
        uint32_t ah0 = *(const uint32_t*)&xs_hi[ra][k0];
        uint32_t ah1 = *(const uint32_t*)&xs_hi[ra + 8][k0];
        uint32_t ah2 = *(const uint32_t*)&xs_hi[ra][k0 + 8];
        uint32_t ah3 = *(const uint32_t*)&xs_hi[ra + 8][k0 + 8];
        uint32_t al0 = *(const uint32_t*)&xs_lo[ra][k0];
        uint32_t al1 = *(const uint32_t*)&xs_lo[ra + 8][k0];
        uint32_t al2 = *(const uint32_t*)&xs_lo[ra][k0 + 8];
        uint32_t al3 = *(const uint32_t*)&xs_lo[ra + 8][k0 + 8];
        #pragma unroll
        for (int c = 0; c < 8; c++) {
            uint32_t bh0 = *(const uint32_t*)&wt_hi[c * 8 + gid][k0];
            uint32_t bh1 = *(const uint32_t*)&wt_hi[c * 8 + gid][k0 + 8];
            uint32_t bl0 = *(const uint32_t*)&wt_lo[c * 8 + gid][k0];
            uint32_t bl1 = *(const uint32_t*)&wt_lo[c * 8 + gid][k0 + 8];
            asm volatile(
                "mma.sync.aligned.m16n8k16.row.col.f32.bf16.bf16.f32 "
                "{%0,%1,%2,%3}, {%4,%5,%6,%7}, {%8,%9}, {%0,%1,%2,%3};"
                : "+f"(d[c][0]), "+f"(d[c][1]), "+f"(d[c][2]), "+f"(d[c][3])
                : "r"(ah0), "r"(ah1), "r"(ah2), "r"(ah3), "r"(bh0), "r"(bh1));
            asm volatile(
                "mma.sync.aligned.m16n8k16.row.col.f32.bf16.bf16.f32 "
                "{%0,%1,%2,%3}, {%4,%5,%6,%7}, {%8,%9}, {%0,%1,%2,%3};"
                : "+f"(d[c][0]), "+f"(d[c][1]), "+f"(d[c][2]), "+f"(d[c][3])
                : "r"(ah0), "r"(ah1), "r"(ah2), "r"(ah3), "r"(bl0), "r"(bl1));
            asm volatile(
                "mma.sync.aligned.m16n8k16.row.col.f32.bf16.bf16.f32 "
                "{%0,%1,%2,%3}, {%4,%5,%6,%7}, {%8,%9}, {%0,%1,%2,%3};"
                : "+f"(d[c][0]), "+f"(d[c][1]), "+f"(d[c][2]), "+f"(d[c][3])
                : "r"(al0), "r"(al1), "r"(al2), "r"(al3), "r"(bh0), "r"(bh1));
        }
    }

    // Epilogue: thread owns rows (base+ra, +8), cols c*8 + tig*2 (+1)
    int row0 = base + ra;
    int row1 = row0 + 8;
    if (row0 < N) {
        float dv = g_dinv[row0];
        #pragma unroll
        for (int c = 0; c < 8; c++) {
            __half2 h = __floats2half2_rn(d[c][0] * dv, d[c][1] * dv);
            *(unsigned*)&g_Bh[(size_t)row0 * 32 + c * 4 + tig] = *(unsigned*)&h;
        }
    }
    if (row1 < N) {
        float dv = g_dinv[row1];
        #pragma unroll
        for (int c = 0; c < 8; c++) {
            __half2 h = __floats2half2_rn(d[c][2] * dv, d[c][3] * dv);
            *(unsigned*)&g_Bh[(size_t)row1 * 32 + c * 4 + tig] = *(unsigned*)&h;
        }
    }
}

// ---------------- aggregation: A[i] = dinv[i]*(B[i] + sum B[src]) + b ----------------
__device__ __forceinline__ void acc_h2(float2& a, __half2 h) {
    float2 f = __half22float2(h);
    a.x += f.x; a.y += f.y;
}

__global__ void __launch_bounds__(256) k_agg(const float* __restrict__ bias,
                                             int relu, int N) {
    int warp = (blockIdx.x * blockDim.x + threadIdx.x) >> 5;
    int lane = threadIdx.x & 31;
    int grp  = lane >> 3;          // 0..3
    int sub  = lane & 7;           // 0..7
    int node = warp * 4 + grp;
    bool active = node < N;
    int nsafe = active ? node : 0;

    const uint4* __restrict__ B4 = (const uint4*)g_Bh;   // B4[node*8 + sub]
    float2 acc[4] = {{0.f,0.f},{0.f,0.f},{0.f,0.f},{0.f,0.f}};

    {   // self loop
        uint4 sv = B4[(size_t)nsafe * 8 + sub];
        acc_h2(acc[0], *(__half2*)&sv.x);
        acc_h2(acc[1], *(__half2*)&sv.y);
        acc_h2(acc[2], *(__half2*)&sv.z);
        acc_h2(acc[3], *(__half2*)&sv.w);
    }

    int beg = active ? g_off[nsafe] : 0;
    int end = active ? g_off[nsafe + 1] : 0;
    int j = beg;
    for (; j + 4 <= end; j += 4) {
        int s0 = g_srcs[j], s1 = g_srcs[j + 1], s2 = g_srcs[j + 2], s3 = g_srcs[j + 3];
        uint4 a = B4[(size_t)s0 * 8 + sub];
        uint4 b = B4[(size_t)s1 * 8 + sub];
        uint4 cc = B4[(size_t)s2 * 8 + sub];
        uint4 d = B4[(size_t)s3 * 8 + sub];
        __half2 t0 = __hadd2(__hadd2(*(__half2*)&a.x, *(__half2*)&b.x),
                             __hadd2(*(__half2*)&cc.x, *(__half2*)&d.x));
        __half2 t1 = __hadd2(__hadd2(*(__half2*)&a.y, *(__half2*)&b.y),
                             __hadd2(*(__half2*)&cc.y, *(__half2*)&d.y));
        __half2 t2 = __hadd2(__hadd2(*(__half2*)&a.z, *(__half2*)&b.z),
                             __hadd2(*(__half2*)&cc.z, *(__half2*)&d.z));
        __half2 t3 = __hadd2(__hadd2(*(__half2*)&a.w, *(__half2*)&b.w),
                             __hadd2(*(__half2*)&cc.w, *(__half2*)&d.w));
        acc_h2(acc[0], t0); acc_h2(acc[1], t1);
        acc_h2(acc[2], t2); acc_h2(acc[3], t3);
    }
    if (j + 2 <= end) {
        int s0 = g_srcs[j], s1 = g_srcs[j + 1];
        uint4 a = B4[(size_t)s0 * 8 + sub];
        uint4 b = B4[(size_t)s1 * 8 + sub];
        acc_h2(acc[0], __hadd2(*(__half2*)&a.x, *(__half2*)&b.x));
        acc_h2(acc[1], __hadd2(*(__half2*)&a.y, *(__half2*)&b.y));
        acc_h2(acc[2], __hadd2(*(__half2*)&a.z, *(__half2*)&b.z));
        acc_h2(acc[3], __hadd2(*(__half2*)&a.w, *(__half2*)&b.w));
        j += 2;
    }
    if (j < end) {
        uint4 a = B4[(size_t)g_srcs[j] * 8 + sub];
        acc_h2(acc[0], *(__half2*)&a.x);
        acc_h2(acc[1], *(__half2*)&a.y);
        acc_h2(acc[2], *(__half2*)&a.z);
        acc_h2(acc[3], *(__half2*)&a.w);
    }

    if (active) {
        float dv = g_dinv[node];
        const float4* bp = (const float4*)(bias + sub * 8);
        float4 b0 = bp[0], b1 = bp[1];
        float4 o0 = make_float4(fmaf(acc[0].x, dv, b0.x), fmaf(acc[0].y, dv, b0.y),
                                fmaf(acc[1].x, dv, b0.z), fmaf(acc[1].y, dv, b0.w));
        float4 o1 = make_float4(fmaf(acc[2].x, dv, b1.x), fmaf(acc[2].y, dv, b1.y),
                                fmaf(acc[3].x, dv, b1.z), fmaf(acc[3].y, dv, b1.w));
        if (relu) {
            o0.x = fmaxf(o0.x, 0.f); o0.y = fmaxf(o0.y, 0.f);
            o0.z = fmaxf(o0.z, 0.f); o0.w = fmaxf(o0.w, 0.f);
            o1.x = fmaxf(o1.x, 0.f); o1.y = fmaxf(o1.y, 0.f);
            o1.z = fmaxf(o1.z, 0.f); o1.w = fmaxf(o1.w, 0.f);
        }
        float4* outp = (float4*)(g_A + (size_t)node * 64 + sub * 8);
        outp[0] = o0; outp[1] = o1;
    }
}

// ---------------- mean pool (batch sorted) ----------------
__global__ void __launch_bounds__(256) k_pool(const int* __restrict__ batch, int N) {
    int warp = (blockIdx.x * blockDim.x + threadIdx.x) >> 5;
    int lane = threadIdx.x & 31;
    int n0 = warp * 32;
    if (n0 >= N) return;
    int nend = min(n0 + 32, N);
    const float2* __restrict__ A2 = (const float2*)g_A;
    float2 acc = make_float2(0.f, 0.f);
    int cur = batch[n0];
    int cnt = 0;
    for (int n = n0; n < nend; n++) {
        int g = batch[n];
        if (g != cur) {
            atomicAdd(&g_sums[cur * 64 + 2 * lane], acc.x);
            atomicAdd(&g_sums[cur * 64 + 2 * lane + 1], acc.y);
            if (lane == 0) atomicAdd(&g_gcnt[cur], cnt);
            acc = make_float2(0.f, 0.f); cnt = 0; cur = g;
        }
        float2 v = A2[(size_t)n * 32 + lane];
        acc.x += v.x; acc.y += v.y; cnt++;
    }
    atomicAdd(&g_sums[cur * 64 + 2 * lane], acc.x);
    atomicAdd(&g_sums[cur * 64 + 2 * lane + 1], acc.y);
    if (lane == 0) atomicAdd(&g_gcnt[cur], cnt);
}

__global__ void k_final(const float* __restrict__ Wlin,
                        const float* __restrict__ blin,
                        float* __restrict__ out) {
    int t = threadIdx.x;
    if (t >= NGRAPH * 2) return;
    int g = t >> 1, o = t & 1;
    float cnt = fmaxf((float)g_gcnt[g], 1.f);
    float s = 0.f;
    #pragma unroll
    for (int f = 0; f < 64; f++) s += g_sums[g * 64 + f] * Wlin[f * 2 + o];
    out[g * 2 + o] = s / cnt + blin[o];
}

// ---------------- launch ----------------
extern "C" void kernel_launch(void* const* d_in, const int* in_sizes, int n_in,
                              void* d_out, int out_size) {
    const float* x     = (const float*)d_in[0];
    const int*   ei    = (const int*)d_in[1];
    const int*   batch = (const int*)d_in[2];
    const float* W1 = (const float*)d_in[3];
    const float* b1 = (const float*)d_in[4];
    const float* W2 = (const float*)d_in[5];
    const float* b2 = (const float*)d_in[6];
    const float* W3 = (const float*)d_in[7];
    const float* b3 = (const float*)d_in[8];
    const float* Wl = (const float*)d_in[9];
    const float* bl = (const float*)d_in[10];
    float* out = (float*)d_out;

    int N = in_sizes[0] / NFEAT;   // 100000
    int E = in_sizes[1] / 2;       // 1000000
    int nb = (N + 1023) / 1024;

    int gemmBlocks = (N + 63) / 64;     // 1563
    int aggBlocks  = (N + 31) / 32;     // 8 warps x 4 nodes per block

    // CSR build; gemm1 at launch slot 4 (profiler captures launch #4)
    k_zero<<<(N + 255) / 256, 256>>>(N);
    k_hist<<<(E + 255) / 256, 256>>>(ei, E);
    k_dinv<<<(N + 255) / 256, 256>>>(N, W1, W2, W3);
    k_gemm_mma<<<gemmBlocks, 128>>>(x, N, 1, 0);    // launch #4
    k_scan1<<<nb, 1024>>>(N);
    k_scan2<<<1, 128>>>(nb, N);
    k_scan3<<<nb, 1024>>>(N);
    k_place<<<(E + 255) / 256, 256>>>(ei, E);

    k_agg<<<aggBlocks, 256>>>(b1, 1, N);
    k_gemm_mma<<<gemmBlocks, 128>>>(nullptr, N, 0, 1);
    k_agg<<<aggBlocks, 256>>>(b2, 1, N);
    k_gemm_mma<<<gemmBlocks, 128>>>(nullptr, N, 0, 2);
    k_agg<<<aggBlocks, 256>>>(b3, 0, N);

    int poolWarps = (N + 31) / 32;
    k_pool<<<(poolWarps + 7) / 8, 256>>>(batch, N);
    k_final<<<1, 128>>>(Wl, bl, out);
}